// round 1
// baseline (speedup 1.0000x reference)
#include <cuda_runtime.h>

#define HH 56
#define WW 56
#define BB 8
#define CC 64
#define HWSZ 3136          // 56*56
#define NPOS 25088         // B*H*W
#define WS_STRIDE 196      // padded weight-smem row stride (floats)

// ---------------- scratch (no cudaMalloc allowed) ----------------
__device__ float g_qkv[(size_t)NPOS * 192];   // [pos][q(64)|k(64)|v(64)]
__device__ float g_wfold[3 * 9 * 64];         // [c(q,k,v)][tap][och]

__device__ __forceinline__ int refl(int i) {
    return i < 0 ? -i : (i >= 56 ? 110 - i : i);
}

// ---------------- kernel 0: fold depthwise-conv weights ----------------
// wfold[c][t][d] = sum_m w_dep[d][m][t] * w_fc[m][c]
__global__ void fold_kernel(const float* __restrict__ w_fc,
                            const float* __restrict__ w_dep) {
    int idx = blockIdx.x * blockDim.x + threadIdx.x;
    if (idx >= 3 * 9 * 64) return;
    int c = idx / 576;
    int r = idx % 576;
    int t = r / 64;
    int d = r % 64;
    float s = 0.f;
#pragma unroll
    for (int m = 0; m < 9; ++m)
        s += w_dep[(d * 9 + m) * 9 + t] * w_fc[m * 3 + c];
    g_wfold[(c * 9 + t) * 64 + d] = s;
}

// ---------------- kernel 1: q,k,v 1x1 convs (GEMM) ----------------
// x: [B][64][HW] -> g_qkv[pos][192], pos = b*HW + p
__global__ __launch_bounds__(256) void qkv_kernel(
    const float* __restrict__ x,
    const float* __restrict__ w1, const float* __restrict__ b1,
    const float* __restrict__ w2, const float* __restrict__ b2,
    const float* __restrict__ w3, const float* __restrict__ b3) {
    extern __shared__ float sm[];
    float* xs = sm;                          // [64][128]
    float* ws = sm + 64 * 128;               // [64 cin][WS_STRIDE] holding 192 oc
    float* bs = sm + 64 * 128 + 64 * WS_STRIDE;  // [192]

    const int tile = blockIdx.x;             // 0..24
    const int b = blockIdx.y;
    const int pos0 = tile * 128;
    const int np = min(128, HWSZ - pos0);
    const int tid = threadIdx.x;

    // load x tile (coalesced per channel row)
    for (int i = tid; i < 64 * 128; i += 256) {
        int cin = i >> 7, p = i & 127;
        xs[i] = (p < np) ? x[((size_t)(b * 64 + cin)) * HWSZ + pos0 + p] : 0.f;
    }
    // load weights transposed: ws[cin][m*64+oc] = w_m[oc][cin]
    for (int i = tid; i < 64 * 64; i += 256) {
        int oc = i >> 6, cin = i & 63;
        ws[cin * WS_STRIDE + oc] = w1[i];
        ws[cin * WS_STRIDE + 64 + oc] = w2[i];
        ws[cin * WS_STRIDE + 128 + oc] = w3[i];
    }
    if (tid < 64) {
        bs[tid] = b1[tid];
        bs[64 + tid] = b2[tid];
        bs[128 + tid] = b3[tid];
    }
    __syncthreads();

    const int og = tid >> 5;   // 0..7 -> 24 output chans each
    const int pg = tid & 31;   // 0..31 -> 4 positions each

    float acc[4][24];
#pragma unroll
    for (int i = 0; i < 4; ++i)
#pragma unroll
        for (int j = 0; j < 24; ++j) acc[i][j] = 0.f;

    const float4* xs4 = (const float4*)xs;
#pragma unroll 4
    for (int cin = 0; cin < 64; ++cin) {
        float4 xv = xs4[cin * 32 + pg];
        const float* wr = ws + cin * WS_STRIDE + og * 24;
#pragma unroll
        for (int j4 = 0; j4 < 6; ++j4) {
            float4 wv = *(const float4*)(wr + j4 * 4);
            int j = j4 * 4;
            acc[0][j + 0] += xv.x * wv.x; acc[0][j + 1] += xv.x * wv.y;
            acc[0][j + 2] += xv.x * wv.z; acc[0][j + 3] += xv.x * wv.w;
            acc[1][j + 0] += xv.y * wv.x; acc[1][j + 1] += xv.y * wv.y;
            acc[1][j + 2] += xv.y * wv.z; acc[1][j + 3] += xv.y * wv.w;
            acc[2][j + 0] += xv.z * wv.x; acc[2][j + 1] += xv.z * wv.y;
            acc[2][j + 2] += xv.z * wv.z; acc[2][j + 3] += xv.z * wv.w;
            acc[3][j + 0] += xv.w * wv.x; acc[3][j + 1] += xv.w * wv.y;
            acc[3][j + 2] += xv.w * wv.z; acc[3][j + 3] += xv.w * wv.w;
        }
    }

#pragma unroll
    for (int i = 0; i < 4; ++i) {
        int p = pg * 4 + i;
        if (p < np) {
            float* dst = g_qkv + ((size_t)(b * HWSZ + pos0 + p)) * 192 + og * 24;
            const float* bb = bs + og * 24;
#pragma unroll
            for (int j4 = 0; j4 < 6; ++j4) {
                float4 v;
                v.x = acc[i][j4 * 4 + 0] + bb[j4 * 4 + 0];
                v.y = acc[i][j4 * 4 + 1] + bb[j4 * 4 + 1];
                v.z = acc[i][j4 * 4 + 2] + bb[j4 * 4 + 2];
                v.w = acc[i][j4 * 4 + 3] + bb[j4 * 4 + 3];
                *(float4*)(dst + j4 * 4) = v;
            }
        }
    }
}

// ---------------- kernel 2: fused attention + conv branch ----------------
// grid (7,7,8): 8x8 spatial tile, 256 threads: 4 threads/pos x 16 ch each.
__global__ __launch_bounds__(256) void attn_kernel(
    const float* __restrict__ wp,
    const float* __restrict__ b_dep,
    const float* __restrict__ rate1,
    const float* __restrict__ rate2,
    float* __restrict__ out) {
    extern __shared__ float sm[];
    float* qs = sm;                // [144][64]
    float* ks = sm + 9216;
    float* vs = sm + 18432;
    float* wf = sm + 27648;        // 1728 folded conv weights

    const int b = blockIdx.z;
    const int ty0 = blockIdx.y * 8;
    const int tx0 = blockIdx.x * 8;
    const int tid = threadIdx.x;

    // halo load: 144 positions x 192 channels, reflect-padded, f4 coalesced
    for (int i = tid; i < 6912; i += 256) {
        int hpos = i / 48;
        int c0 = (i % 48) * 4;
        int hy = hpos / 12, hx = hpos % 12;
        int gy = refl(ty0 + hy - 2);
        int gx = refl(tx0 + hx - 2);
        float4 v = *(const float4*)(g_qkv +
            ((size_t)(b * HWSZ + gy * 56 + gx)) * 192 + c0);
        float* dst;
        if (c0 < 64)       dst = qs + hpos * 64 + c0;
        else if (c0 < 128) dst = ks + hpos * 64 + (c0 - 64);
        else               dst = vs + hpos * 64 + (c0 - 128);
        *(float4*)dst = v;
    }
    for (int i = tid; i < 1728; i += 256) wf[i] = g_wfold[i];
    __syncthreads();

    const int pos = tid >> 2;           // 0..63
    const int sub = tid & 3;            // channel quarter
    const int ty = pos >> 3, tx = pos & 7;
    const int gy = ty0 + ty, gx = tx0 + tx;
    const int d0 = sub * 16;
    const int chidx = (ty + 2) * 12 + (tx + 2);

    // q into registers (raw; scaling folded in later)
    float qr[16];
    {
        const float4* qp = (const float4*)(qs + chidx * 64 + d0);
#pragma unroll
        for (int i = 0; i < 4; ++i) {
            float4 v = qp[i];
            qr[i * 4 + 0] = v.x; qr[i * 4 + 1] = v.y;
            qr[i * 4 + 2] = v.z; qr[i * 4 + 3] = v.w;
        }
    }

    // 25 window dots (partial over 16 channels)
    float acc[25];
#pragma unroll
    for (int j = 0; j < 25; ++j) {
        int off = (j / 5 - 2) * 12 + (j % 5 - 2);
        const float4* kp = (const float4*)(ks + (chidx + off) * 64 + d0);
        float s = 0.f;
#pragma unroll
        for (int i = 0; i < 4; ++i) {
            float4 kv = kp[i];
            s += qr[i * 4 + 0] * kv.x + qr[i * 4 + 1] * kv.y +
                 qr[i * 4 + 2] * kv.z + qr[i * 4 + 3] * kv.w;
        }
        acc[j] = s;
    }
    // PE dots: a = q.wp[:,0], bb = q.wp[:,1]  (bp term cancels)
    float a = 0.f, bbq = 0.f;
#pragma unroll
    for (int d = 0; d < 16; ++d) {
        float2 w = *(const float2*)(wp + (d0 + d) * 2);
        a += qr[d] * w.x;
        bbq += qr[d] * w.y;
    }
    // quad butterfly reduce (channel quarters are adjacent lanes)
#pragma unroll
    for (int s = 1; s < 4; s <<= 1) {
#pragma unroll
        for (int j = 0; j < 25; ++j)
            acc[j] += __shfl_xor_sync(0xffffffffu, acc[j], s);
        a += __shfl_xor_sync(0xffffffffu, a, s);
        bbq += __shfl_xor_sync(0xffffffffu, bbq, s);
    }

    // PE correction + scaling + softmax (over 25 taps)
    const float scaling = 0.125f;        // 64^-0.5
    const float lstep = 2.f / 55.f;
    float mx = -1e30f;
#pragma unroll
    for (int j = 0; j < 25; ++j) {
        int dy = j / 5 - 2, dx = j % 5 - 2;
        int gyj = refl(gy + dy), gxj = refl(gx + dx);
        float t = scaling * (acc[j] + a * ((float)(gx - gxj) * lstep) +
                             bbq * ((float)(gy - gyj) * lstep));
        acc[j] = t;
        mx = fmaxf(mx, t);
    }
    float ssum = 0.f;
#pragma unroll
    for (int j = 0; j < 25; ++j) {
        float e = __expf(acc[j] - mx);
        acc[j] = e;
        ssum += e;
    }
    float inv = 1.f / ssum;

    // attention output: sum_j att_j * v_j  (16 channels)
    float oa[16];
#pragma unroll
    for (int d = 0; d < 16; ++d) oa[d] = 0.f;
#pragma unroll
    for (int j = 0; j < 25; ++j) {
        int off = (j / 5 - 2) * 12 + (j % 5 - 2);
        float w = acc[j];
        const float4* vp = (const float4*)(vs + (chidx + off) * 64 + d0);
#pragma unroll
        for (int i = 0; i < 4; ++i) {
            float4 vv = vp[i];
            oa[i * 4 + 0] += w * vv.x; oa[i * 4 + 1] += w * vv.y;
            oa[i * 4 + 2] += w * vv.z; oa[i * 4 + 3] += w * vv.w;
        }
    }

    // folded conv branch: 3 depthwise 3x3 convs on q,k,v (zero padding)
    float ocv[16];
#pragma unroll
    for (int d = 0; d < 16; ++d) ocv[d] = 0.f;
#pragma unroll
    for (int t = 0; t < 9; ++t) {
        int dy = t / 3 - 1, dx = t % 3 - 1;
        int yy = gy + dy, xx = gx + dx;
        if (yy >= 0 && yy < 56 && xx >= 0 && xx < 56) {
            int hoff = (chidx + dy * 12 + dx) * 64 + d0;
            const float4* qp = (const float4*)(qs + hoff);
            const float4* kp = (const float4*)(ks + hoff);
            const float4* vp = (const float4*)(vs + hoff);
            const float4* wa = (const float4*)(wf + (0 * 9 + t) * 64 + d0);
            const float4* wb = (const float4*)(wf + (1 * 9 + t) * 64 + d0);
            const float4* wc = (const float4*)(wf + (2 * 9 + t) * 64 + d0);
#pragma unroll
            for (int i = 0; i < 4; ++i) {
                float4 qv = qp[i], kv = kp[i], vv = vp[i];
                float4 av = wa[i], bv = wb[i], cv = wc[i];
                ocv[i * 4 + 0] += av.x * qv.x + bv.x * kv.x + cv.x * vv.x;
                ocv[i * 4 + 1] += av.y * qv.y + bv.y * kv.y + cv.y * vv.y;
                ocv[i * 4 + 2] += av.z * qv.z + bv.z * kv.z + cv.z * vv.z;
                ocv[i * 4 + 3] += av.w * qv.w + bv.w * kv.w + cv.w * vv.w;
            }
        }
    }

    const float r1 = rate1[0];
    const float r2 = rate2[0];
#pragma unroll
    for (int d = 0; d < 16; ++d) {
        float res = r1 * (oa[d] * inv) + r2 * (ocv[d] + b_dep[d0 + d]);
        out[((size_t)(b * 64 + d0 + d) * 56 + gy) * 56 + gx] = res;
    }
}

// ---------------- launch ----------------
extern "C" void kernel_launch(void* const* d_in, const int* in_sizes, int n_in,
                              void* d_out, int out_size) {
    const float* x    = (const float*)d_in[0];
    const float* w1   = (const float*)d_in[1];
    const float* b1   = (const float*)d_in[2];
    const float* w2   = (const float*)d_in[3];
    const float* b2   = (const float*)d_in[4];
    const float* w3   = (const float*)d_in[5];
    const float* b3   = (const float*)d_in[6];
    const float* wp   = (const float*)d_in[7];
    // d_in[8] = bp (cancels analytically)
    const float* w_fc = (const float*)d_in[9];
    const float* w_dep = (const float*)d_in[10];
    const float* b_dep = (const float*)d_in[11];
    const float* rate1 = (const float*)d_in[12];
    const float* rate2 = (const float*)d_in[13];
    float* out = (float*)d_out;

    const int qkv_smem = (64 * 128 + 64 * WS_STRIDE + 192) * 4;
    const int att_smem = (3 * 144 * 64 + 1728) * 4;
    cudaFuncSetAttribute(qkv_kernel, cudaFuncAttributeMaxDynamicSharedMemorySize, qkv_smem);
    cudaFuncSetAttribute(attn_kernel, cudaFuncAttributeMaxDynamicSharedMemorySize, att_smem);

    fold_kernel<<<7, 256>>>(w_fc, w_dep);
    qkv_kernel<<<dim3(25, 8), 256, qkv_smem>>>(x, w1, b1, w2, b2, w3, b3);
    attn_kernel<<<dim3(7, 7, 8), 256, att_smem>>>(wp, b_dep, rate1, rate2, out);
}

// round 2
// speedup vs baseline: 1.3746x; 1.3746x over previous
#include <cuda_runtime.h>

#define HWSZ 3136          // 56*56
#define NPOS 25088         // B*H*W
#define WS_STRIDE 196      // padded weight-smem row stride (floats)
#define PSTR 80            // attn smem per-position stride (floats): 320B == 64B mod 128B

// ---------------- scratch (no cudaMalloc allowed) ----------------
__device__ float g_qkv[(size_t)NPOS * 192];   // [pos][q(64)|k(64)|v(64)]

__device__ __forceinline__ int refl(int i) {
    return i < 0 ? -i : (i >= 56 ? 110 - i : i);
}
// packed f32x2 helpers (Blackwell; ptxas never emits these from C++)
__device__ __forceinline__ unsigned long long bc2(float x) {
    unsigned long long r;
    asm("mov.b64 %0,{%1,%1};" : "=l"(r) : "f"(x));
    return r;
}
__device__ __forceinline__ unsigned long long pk2(float lo, float hi) {
    unsigned long long r;
    asm("mov.b64 %0,{%1,%2};" : "=l"(r) : "f"(lo), "f"(hi));
    return r;
}
__device__ __forceinline__ void fma2(unsigned long long& d, unsigned long long a,
                                     unsigned long long b) {
    asm("fma.rn.f32x2 %0,%1,%2,%0;" : "+l"(d) : "l"(a), "l"(b));
}
__device__ __forceinline__ float2 up2(unsigned long long v) {
    float2 r;
    asm("mov.b64 {%0,%1},%2;" : "=f"(r.x), "=f"(r.y) : "l"(v));
    return r;
}

// ---------------- kernel 1: q,k,v 1x1 convs (GEMM, f32x2 packed) ----------------
// x: [B][64][HW] -> g_qkv[pos][192], pos = b*HW + p
__global__ __launch_bounds__(512) void qkv_kernel(
    const float* __restrict__ x,
    const float* __restrict__ w1, const float* __restrict__ b1,
    const float* __restrict__ w2, const float* __restrict__ b2,
    const float* __restrict__ w3, const float* __restrict__ b3) {
    extern __shared__ float sm[];
    float* xs = sm;                          // [64][128]
    float* ws = sm + 8192;                   // [64 cin][WS_STRIDE] holding 192 oc
    float* bs = sm + 8192 + 64 * WS_STRIDE;  // [192]

    const int tile = blockIdx.x;             // 0..24
    const int b = blockIdx.y;
    const int pos0 = tile * 128;
    const int np = min(128, HWSZ - pos0);
    const int tid = threadIdx.x;

    for (int i = tid; i < 8192; i += 512) {
        int cin = i >> 7, p = i & 127;
        xs[i] = (p < np) ? x[((size_t)(b * 64 + cin)) * HWSZ + pos0 + p] : 0.f;
    }
    for (int i = tid; i < 4096; i += 512) {
        int oc = i >> 6, cin = i & 63;
        ws[cin * WS_STRIDE + oc] = w1[i];
        ws[cin * WS_STRIDE + 64 + oc] = w2[i];
        ws[cin * WS_STRIDE + 128 + oc] = w3[i];
    }
    if (tid < 192)
        bs[tid] = (tid < 64) ? b1[tid] : (tid < 128 ? b2[tid - 64] : b3[tid - 128]);
    __syncthreads();

    const int og = tid >> 4;   // 0..31 -> 6 output chans each
    const int pg = tid & 15;   // float4 slots pg and pg+16 -> 8 positions each

    unsigned long long acc[8][3];
#pragma unroll
    for (int p = 0; p < 8; ++p)
#pragma unroll
        for (int q = 0; q < 3; ++q) acc[p][q] = 0ull;

    const float4* xs4 = (const float4*)xs;
#pragma unroll 2
    for (int cin = 0; cin < 64; ++cin) {
        float4 xa = xs4[cin * 32 + pg];          // positions 4pg..4pg+3
        float4 xb = xs4[cin * 32 + 16 + pg];     // positions 64+4pg..+3
        const float2* wr = (const float2*)(ws + cin * WS_STRIDE + og * 6);
        float2 wa = wr[0], wb = wr[1], wc = wr[2];
        unsigned long long wq0 = pk2(wa.x, wa.y);
        unsigned long long wq1 = pk2(wb.x, wb.y);
        unsigned long long wq2 = pk2(wc.x, wc.y);
        unsigned long long xp[8] = {bc2(xa.x), bc2(xa.y), bc2(xa.z), bc2(xa.w),
                                    bc2(xb.x), bc2(xb.y), bc2(xb.z), bc2(xb.w)};
#pragma unroll
        for (int p = 0; p < 8; ++p) {
            fma2(acc[p][0], xp[p], wq0);
            fma2(acc[p][1], xp[p], wq1);
            fma2(acc[p][2], xp[p], wq2);
        }
    }

    float bl[6];
#pragma unroll
    for (int j = 0; j < 6; ++j) bl[j] = bs[og * 6 + j];

#pragma unroll
    for (int p = 0; p < 8; ++p) {
        int pos = (p < 4) ? (4 * pg + p) : (64 + 4 * pg + (p - 4));
        if (pos < np) {
            float* dst = g_qkv + ((size_t)(b * HWSZ + pos0 + pos)) * 192 + og * 6;
            float2 v0 = up2(acc[p][0]);
            float2 v1 = up2(acc[p][1]);
            float2 v2 = up2(acc[p][2]);
            float2 o0 = {v0.x + bl[0], v0.y + bl[1]};
            float2 o1 = {v1.x + bl[2], v1.y + bl[3]};
            float2 o2 = {v2.x + bl[4], v2.y + bl[5]};
            *(float2*)(dst + 0) = o0;
            *(float2*)(dst + 2) = o1;
            *(float2*)(dst + 4) = o2;
        }
    }
}

// ---------------- kernel 2: fused attention + conv branch ----------------
// grid (7,7,8): 8x8 spatial tile, 256 threads: 4 threads/pos.
// sub-thread s handles interleaved float4 chunks {s, s+4, s+8, s+12}
// => channels 16*i + 4*s + j. Conflict-free with PSTR=80.
__global__ __launch_bounds__(256) void attn_kernel(
    const float* __restrict__ wp,
    const float* __restrict__ w_fc,
    const float* __restrict__ w_dep,
    const float* __restrict__ b_dep,
    const float* __restrict__ rate1,
    const float* __restrict__ rate2,
    float* __restrict__ out) {
    extern __shared__ float sm[];
    float* qs = sm;                      // [144][PSTR]
    float* ks = sm + 144 * PSTR;
    float* vs = sm + 2 * 144 * PSTR;
    float* wf = sm + 3 * 144 * PSTR;     // [3][9][64] folded conv weights

    const int b = blockIdx.z;
    const int ty0 = blockIdx.y * 8;
    const int tx0 = blockIdx.x * 8;
    const int tid = threadIdx.x;

    // fold depthwise-conv weights in-kernel:
    // wf[c][t][d] = sum_m w_dep[d][m][t] * w_fc[m][c]
    for (int i = tid; i < 1728; i += 256) {
        int c = i / 576, r = i % 576, t = r >> 6, d = r & 63;
        float s = 0.f;
#pragma unroll
        for (int m = 0; m < 9; ++m)
            s += w_dep[(d * 9 + m) * 9 + t] * w_fc[m * 3 + c];
        wf[i] = s;
    }

    // halo load: 144 positions x 192 channels, reflect-padded, f4 coalesced
    for (int i = tid; i < 6912; i += 256) {
        int hpos = i / 48;
        int c4 = i % 48;
        int hy = hpos / 12, hx = hpos % 12;
        int gy = refl(ty0 + hy - 2);
        int gx = refl(tx0 + hx - 2);
        float4 v = *(const float4*)(g_qkv +
            ((size_t)(b * HWSZ + gy * 56 + gx)) * 192 + c4 * 4);
        float* arr = (c4 < 16) ? qs : (c4 < 32 ? ks : vs);
        *(float4*)(arr + hpos * PSTR + (c4 & 15) * 4) = v;
    }
    __syncthreads();

    const int pos = tid >> 2;           // 0..63
    const int s = tid & 3;              // interleaved channel quarter
    const int ty = pos >> 3, tx = pos & 7;
    const int gy = ty0 + ty, gx = tx0 + tx;
    const int chidx = (ty + 2) * 12 + (tx + 2);
    const int sb = s * 4;               // float offset of sub's first chunk

    // q into registers (raw; scaling folded later). qr[i*4+j] = ch 16i+4s+j
    float qr[16];
    {
        const float* qb = qs + chidx * PSTR + sb;
#pragma unroll
        for (int i = 0; i < 4; ++i) {
            float4 v = *(const float4*)(qb + i * 16);
            qr[i * 4 + 0] = v.x; qr[i * 4 + 1] = v.y;
            qr[i * 4 + 2] = v.z; qr[i * 4 + 3] = v.w;
        }
    }

    // 25 window dots (partial over this thread's 16 channels)
    float acc[25];
#pragma unroll
    for (int j = 0; j < 25; ++j) {
        int off = (j / 5 - 2) * 12 + (j % 5 - 2);
        const float* kb = ks + (chidx + off) * PSTR + sb;
        float sum = 0.f;
#pragma unroll
        for (int i = 0; i < 4; ++i) {
            float4 kv = *(const float4*)(kb + i * 16);
            sum += qr[i * 4 + 0] * kv.x + qr[i * 4 + 1] * kv.y +
                   qr[i * 4 + 2] * kv.z + qr[i * 4 + 3] * kv.w;
        }
        acc[j] = sum;
    }
    // PE dots: a = q.wp[:,0], bq = q.wp[:,1]  (bp term cancels analytically)
    float a = 0.f, bq = 0.f;
#pragma unroll
    for (int i = 0; i < 4; ++i)
#pragma unroll
        for (int j = 0; j < 4; ++j) {
            int ch = 16 * i + 4 * s + j;
            float2 w = __ldg((const float2*)wp + ch);
            a += qr[i * 4 + j] * w.x;
            bq += qr[i * 4 + j] * w.y;
        }
    // quad butterfly reduce (channel quarters are adjacent lanes)
#pragma unroll
    for (int st = 1; st < 4; st <<= 1) {
#pragma unroll
        for (int j = 0; j < 25; ++j)
            acc[j] += __shfl_xor_sync(0xffffffffu, acc[j], st);
        a += __shfl_xor_sync(0xffffffffu, a, st);
        bq += __shfl_xor_sync(0xffffffffu, bq, st);
    }

    // PE correction + scaling + softmax (over 25 taps)
    const float scaling = 0.125f;        // 64^-0.5
    const float lstep = 2.f / 55.f;
    float mx = -1e30f;
#pragma unroll
    for (int j = 0; j < 25; ++j) {
        int dy = j / 5 - 2, dx = j % 5 - 2;
        int gyj = refl(gy + dy), gxj = refl(gx + dx);
        float t = scaling * (acc[j] + a * ((float)(gx - gxj) * lstep) +
                             bq * ((float)(gy - gyj) * lstep));
        acc[j] = t;
        mx = fmaxf(mx, t);
    }
    float ssum = 0.f;
#pragma unroll
    for (int j = 0; j < 25; ++j) {
        float e = __expf(acc[j] - mx);
        acc[j] = e;
        ssum += e;
    }
    float inv = 1.f / ssum;

    // attention output: sum_j att_j * v_j  (16 channels)
    float oa[16];
#pragma unroll
    for (int d = 0; d < 16; ++d) oa[d] = 0.f;
#pragma unroll
    for (int j = 0; j < 25; ++j) {
        int off = (j / 5 - 2) * 12 + (j % 5 - 2);
        float w = acc[j];
        const float* vb = vs + (chidx + off) * PSTR + sb;
#pragma unroll
        for (int i = 0; i < 4; ++i) {
            float4 vv = *(const float4*)(vb + i * 16);
            oa[i * 4 + 0] += w * vv.x; oa[i * 4 + 1] += w * vv.y;
            oa[i * 4 + 2] += w * vv.z; oa[i * 4 + 3] += w * vv.w;
        }
    }

    // folded conv branch: 3 depthwise 3x3 convs on q,k,v (zero padding)
    float ocv[16];
#pragma unroll
    for (int d = 0; d < 16; ++d) ocv[d] = 0.f;
#pragma unroll
    for (int t = 0; t < 9; ++t) {
        int dy = t / 3 - 1, dx = t % 3 - 1;
        int yy = gy + dy, xx = gx + dx;
        if (yy >= 0 && yy < 56 && xx >= 0 && xx < 56) {
            int hoff = (chidx + dy * 12 + dx) * PSTR + sb;
            const float* qp = qs + hoff;
            const float* kp = ks + hoff;
            const float* vp = vs + hoff;
            const float* wa = wf + (0 * 9 + t) * 64 + sb;
            const float* wb = wf + (1 * 9 + t) * 64 + sb;
            const float* wc = wf + (2 * 9 + t) * 64 + sb;
#pragma unroll
            for (int i = 0; i < 4; ++i) {
                float4 qv = *(const float4*)(qp + i * 16);
                float4 kv = *(const float4*)(kp + i * 16);
                float4 vv = *(const float4*)(vp + i * 16);
                float4 av = *(const float4*)(wa + i * 16);
                float4 bv = *(const float4*)(wb + i * 16);
                float4 cv = *(const float4*)(wc + i * 16);
                ocv[i * 4 + 0] += av.x * qv.x + bv.x * kv.x + cv.x * vv.x;
                ocv[i * 4 + 1] += av.y * qv.y + bv.y * kv.y + cv.y * vv.y;
                ocv[i * 4 + 2] += av.z * qv.z + bv.z * kv.z + cv.z * vv.z;
                ocv[i * 4 + 3] += av.w * qv.w + bv.w * kv.w + cv.w * vv.w;
            }
        }
    }

    const float r1 = rate1[0];
    const float r2 = rate2[0];
#pragma unroll
    for (int i = 0; i < 4; ++i)
#pragma unroll
        for (int j = 0; j < 4; ++j) {
            int ch = 16 * i + 4 * s + j;
            float res = r1 * (oa[i * 4 + j] * inv) +
                        r2 * (ocv[i * 4 + j] + __ldg(b_dep + ch));
            out[((size_t)(b * 64 + ch) * 56 + gy) * 56 + gx] = res;
        }
}

// ---------------- launch ----------------
extern "C" void kernel_launch(void* const* d_in, const int* in_sizes, int n_in,
                              void* d_out, int out_size) {
    const float* x    = (const float*)d_in[0];
    const float* w1   = (const float*)d_in[1];
    const float* b1   = (const float*)d_in[2];
    const float* w2   = (const float*)d_in[3];
    const float* b2   = (const float*)d_in[4];
    const float* w3   = (const float*)d_in[5];
    const float* b3   = (const float*)d_in[6];
    const float* wp   = (const float*)d_in[7];
    // d_in[8] = bp (cancels analytically)
    const float* w_fc = (const float*)d_in[9];
    const float* w_dep = (const float*)d_in[10];
    const float* b_dep = (const float*)d_in[11];
    const float* rate1 = (const float*)d_in[12];
    const float* rate2 = (const float*)d_in[13];
    float* out = (float*)d_out;

    const int qkv_smem = (8192 + 64 * WS_STRIDE + 192) * 4;
    const int att_smem = (3 * 144 * PSTR + 1728) * 4;
    cudaFuncSetAttribute(qkv_kernel, cudaFuncAttributeMaxDynamicSharedMemorySize, qkv_smem);
    cudaFuncSetAttribute(attn_kernel, cudaFuncAttributeMaxDynamicSharedMemorySize, att_smem);

    qkv_kernel<<<dim3(25, 8), 512, qkv_smem>>>(x, w1, b1, w2, b2, w3, b3);
    attn_kernel<<<dim3(7, 7, 8), 256, att_smem>>>(wp, w_fc, w_dep, b_dep, rate1, rate2, out);
}

// round 3
// speedup vs baseline: 1.7018x; 1.2380x over previous
#include <cuda_runtime.h>

#define HWSZ 3136          // 56*56
#define NPOS 25088         // B*H*W
#define WS_STRIDE 196      // padded weight-smem row stride (floats)
#define PSTR 80            // attn smem per-position stride (floats): 320B == 64B mod 128B

// ---------------- scratch (no cudaMalloc allowed) ----------------
__device__ float g_qkv[(size_t)NPOS * 192];   // [pos][q(64)|k(64)|v(64)]

__device__ __forceinline__ int refl(int i) {
    return i < 0 ? -i : (i >= 56 ? 110 - i : i);
}
// packed f32x2 helpers (Blackwell; ptxas never emits these from C++)
__device__ __forceinline__ unsigned long long bc2(float x) {
    unsigned long long r;
    asm("mov.b64 %0,{%1,%1};" : "=l"(r) : "f"(x));
    return r;
}
__device__ __forceinline__ unsigned long long pk2(float lo, float hi) {
    unsigned long long r;
    asm("mov.b64 %0,{%1,%2};" : "=l"(r) : "f"(lo), "f"(hi));
    return r;
}
__device__ __forceinline__ void fma2(unsigned long long& d, unsigned long long a,
                                     unsigned long long b) {
    asm("fma.rn.f32x2 %0,%1,%2,%0;" : "+l"(d) : "l"(a), "l"(b));
}
__device__ __forceinline__ float2 up2(unsigned long long v) {
    float2 r;
    asm("mov.b64 {%0,%1},%2;" : "=f"(r.x), "=f"(r.y) : "l"(v));
    return r;
}

// ---------------- kernel 1: q,k,v 1x1 convs (GEMM, f32x2 packed) ----------------
// x: [B][64][HW] -> g_qkv[pos][192].  Block: 256 thr, 64-pos tile (49x8 grid).
// warp w handles positions w*8..w*8+7; lane og handles oc group og*6..og*6+5.
__global__ __launch_bounds__(256) void qkv_kernel(
    const float* __restrict__ x,
    const float* __restrict__ w1, const float* __restrict__ b1,
    const float* __restrict__ w2, const float* __restrict__ b2,
    const float* __restrict__ w3, const float* __restrict__ b3) {
    extern __shared__ float sm[];
    float* xs = sm;                          // [64 cin][64 pos]
    float* ws = sm + 4096;                   // [64 cin][WS_STRIDE] holding 192 oc
    float* bs = sm + 4096 + 64 * WS_STRIDE;  // [192]

    const int b = blockIdx.y;
    const int pos0 = blockIdx.x * 64;        // 49 tiles * 64 = 3136 exact
    const int tid = threadIdx.x;

    for (int i = tid; i < 4096; i += 256) {
        int cin = i >> 6, p = i & 63;
        xs[i] = x[((size_t)(b * 64 + cin)) * HWSZ + pos0 + p];
    }
    for (int i = tid; i < 4096; i += 256) {
        int oc = i >> 6, cin = i & 63;
        ws[cin * WS_STRIDE + oc] = w1[i];
        ws[cin * WS_STRIDE + 64 + oc] = w2[i];
        ws[cin * WS_STRIDE + 128 + oc] = w3[i];
    }
    if (tid < 192)
        bs[tid] = (tid < 64) ? b1[tid] : (tid < 128 ? b2[tid - 64] : b3[tid - 128]);
    __syncthreads();

    const int w = tid >> 5;    // warp 0..7 -> 8 positions
    const int og = tid & 31;   // lane -> 6 output chans

    unsigned long long acc[8][3];
#pragma unroll
    for (int p = 0; p < 8; ++p)
#pragma unroll
        for (int q = 0; q < 3; ++q) acc[p][q] = 0ull;

    const float4* xs4 = (const float4*)xs;
#pragma unroll 2
    for (int cin = 0; cin < 64; ++cin) {
        float4 xa = xs4[cin * 16 + w * 2];       // positions 8w..8w+3 (broadcast)
        float4 xb = xs4[cin * 16 + w * 2 + 1];   // positions 8w+4..8w+7
        const float2* wr = (const float2*)(ws + cin * WS_STRIDE + og * 6);
        float2 wa = wr[0], wb = wr[1], wc = wr[2];
        unsigned long long wq0 = pk2(wa.x, wa.y);
        unsigned long long wq1 = pk2(wb.x, wb.y);
        unsigned long long wq2 = pk2(wc.x, wc.y);
        unsigned long long xp[8] = {bc2(xa.x), bc2(xa.y), bc2(xa.z), bc2(xa.w),
                                    bc2(xb.x), bc2(xb.y), bc2(xb.z), bc2(xb.w)};
#pragma unroll
        for (int p = 0; p < 8; ++p) {
            fma2(acc[p][0], xp[p], wq0);
            fma2(acc[p][1], xp[p], wq1);
            fma2(acc[p][2], xp[p], wq2);
        }
    }

    float bl[6];
#pragma unroll
    for (int j = 0; j < 6; ++j) bl[j] = bs[og * 6 + j];

#pragma unroll
    for (int p = 0; p < 8; ++p) {
        // lanes og=0..31 cover 768B contiguously per position -> coalesced
        float* dst = g_qkv + ((size_t)(b * HWSZ + pos0 + w * 8 + p)) * 192 + og * 6;
        float2 v0 = up2(acc[p][0]);
        float2 v1 = up2(acc[p][1]);
        float2 v2 = up2(acc[p][2]);
        float2 o0 = {v0.x + bl[0], v0.y + bl[1]};
        float2 o1 = {v1.x + bl[2], v1.y + bl[3]};
        float2 o2 = {v2.x + bl[4], v2.y + bl[5]};
        *(float2*)(dst + 0) = o0;
        *(float2*)(dst + 2) = o1;
        *(float2*)(dst + 4) = o2;
    }
}

// ---------------- kernel 2: fused attention + conv branch ----------------
// grid (7,7,8): 8x8 spatial tile, 512 threads: 8 threads/pos x 8 ch each.
// sub s handles float4 chunks at byte offsets s*16 and 128+s*16 of the 256B
// position block => channels i*32 + s*4 + j. Conflict-free with PSTR=80.
__global__ __launch_bounds__(512) void attn_kernel(
    const float* __restrict__ wp,
    const float* __restrict__ w_fc,
    const float* __restrict__ w_dep,
    const float* __restrict__ b_dep,
    const float* __restrict__ rate1,
    const float* __restrict__ rate2,
    float* __restrict__ out) {
    extern __shared__ float sm[];
    float* qs = sm;                      // [144][PSTR]
    float* ks = sm + 144 * PSTR;
    float* vs = sm + 2 * 144 * PSTR;
    float* wf = sm + 3 * 144 * PSTR;     // [3][9][64] folded conv weights

    const int b = blockIdx.z;
    const int ty0 = blockIdx.y * 8;
    const int tx0 = blockIdx.x * 8;
    const int tid = threadIdx.x;

    // fold depthwise-conv weights in-kernel:
    // wf[c][t][d] = sum_m w_dep[d][m][t] * w_fc[m][c]
    for (int i = tid; i < 1728; i += 512) {
        int c = i / 576, r = i % 576, t = r >> 6, d = r & 63;
        float s = 0.f;
#pragma unroll
        for (int m = 0; m < 9; ++m)
            s += w_dep[(d * 9 + m) * 9 + t] * w_fc[m * 3 + c];
        wf[i] = s;
    }

    // halo load: 144 positions x 192 channels, reflect-padded, f4 coalesced
    for (int i = tid; i < 6912; i += 512) {
        int hpos = i / 48;
        int c4 = i % 48;
        int hy = hpos / 12, hx = hpos % 12;
        int gy = refl(ty0 + hy - 2);
        int gx = refl(tx0 + hx - 2);
        float4 v = *(const float4*)(g_qkv +
            ((size_t)(b * HWSZ + gy * 56 + gx)) * 192 + c4 * 4);
        float* arr = (c4 < 16) ? qs : (c4 < 32 ? ks : vs);
        *(float4*)(arr + hpos * PSTR + (c4 & 15) * 4) = v;
    }
    __syncthreads();

    const int pos = tid >> 3;           // 0..63
    const int s = tid & 7;              // channel sub (interleaved chunks)
    const int ty = pos >> 3, tx = pos & 7;
    const int gy = ty0 + ty, gx = tx0 + tx;
    const int chidx = (ty + 2) * 12 + (tx + 2);
    const int sb = s * 4;               // float offset of sub's first chunk

    // q into registers. qr[i*4+j] = channel i*32 + s*4 + j
    float qr[8];
    {
        const float* qb = qs + chidx * PSTR + sb;
#pragma unroll
        for (int i = 0; i < 2; ++i) {
            float4 v = *(const float4*)(qb + i * 32);
            qr[i * 4 + 0] = v.x; qr[i * 4 + 1] = v.y;
            qr[i * 4 + 2] = v.z; qr[i * 4 + 3] = v.w;
        }
    }

    // 25 window dots (partial over this thread's 8 channels)
    float acc[25];
#pragma unroll
    for (int j = 0; j < 25; ++j) {
        int off = (j / 5 - 2) * 12 + (j % 5 - 2);
        const float* kb = ks + (chidx + off) * PSTR + sb;
        float sum = 0.f;
#pragma unroll
        for (int i = 0; i < 2; ++i) {
            float4 kv = *(const float4*)(kb + i * 32);
            sum += qr[i * 4 + 0] * kv.x + qr[i * 4 + 1] * kv.y +
                   qr[i * 4 + 2] * kv.z + qr[i * 4 + 3] * kv.w;
        }
        acc[j] = sum;
    }
    // PE dots: a = q.wp[:,0], bq = q.wp[:,1]  (bp term cancels analytically)
    float a = 0.f, bq = 0.f;
#pragma unroll
    for (int i = 0; i < 2; ++i)
#pragma unroll
        for (int j = 0; j < 4; ++j) {
            int ch = i * 32 + s * 4 + j;
            float2 w = __ldg((const float2*)wp + ch);
            a += qr[i * 4 + j] * w.x;
            bq += qr[i * 4 + j] * w.y;
        }
    // 8-lane butterfly reduce (subs are adjacent lanes)
#pragma unroll
    for (int st = 1; st < 8; st <<= 1) {
#pragma unroll
        for (int j = 0; j < 25; ++j)
            acc[j] += __shfl_xor_sync(0xffffffffu, acc[j], st);
        a += __shfl_xor_sync(0xffffffffu, a, st);
        bq += __shfl_xor_sync(0xffffffffu, bq, st);
    }

    // PE correction + scaling + softmax (over 25 taps)
    const float scaling = 0.125f;        // 64^-0.5
    const float lstep = 2.f / 55.f;
    float mx = -1e30f;
#pragma unroll
    for (int j = 0; j < 25; ++j) {
        int dy = j / 5 - 2, dx = j % 5 - 2;
        int gyj = refl(gy + dy), gxj = refl(gx + dx);
        float t = scaling * (acc[j] + a * ((float)(gx - gxj) * lstep) +
                             bq * ((float)(gy - gyj) * lstep));
        acc[j] = t;
        mx = fmaxf(mx, t);
    }
    float ssum = 0.f;
#pragma unroll
    for (int j = 0; j < 25; ++j) {
        float e = __expf(acc[j] - mx);
        acc[j] = e;
        ssum += e;
    }
    float inv = 1.f / ssum;

    // attention output: sum_j att_j * v_j  (8 channels)
    float oa[8];
#pragma unroll
    for (int d = 0; d < 8; ++d) oa[d] = 0.f;
#pragma unroll
    for (int j = 0; j < 25; ++j) {
        int off = (j / 5 - 2) * 12 + (j % 5 - 2);
        float w = acc[j];
        const float* vb = vs + (chidx + off) * PSTR + sb;
#pragma unroll
        for (int i = 0; i < 2; ++i) {
            float4 vv = *(const float4*)(vb + i * 32);
            oa[i * 4 + 0] += w * vv.x; oa[i * 4 + 1] += w * vv.y;
            oa[i * 4 + 2] += w * vv.z; oa[i * 4 + 3] += w * vv.w;
        }
    }

    // folded conv branch: 3 depthwise 3x3 convs on q,k,v (zero padding)
    float ocv[8];
#pragma unroll
    for (int d = 0; d < 8; ++d) ocv[d] = 0.f;
#pragma unroll
    for (int t = 0; t < 9; ++t) {
        int dy = t / 3 - 1, dx = t % 3 - 1;
        int yy = gy + dy, xx = gx + dx;
        if (yy >= 0 && yy < 56 && xx >= 0 && xx < 56) {
            int hoff = (chidx + dy * 12 + dx) * PSTR + sb;
            const float* qp = qs + hoff;
            const float* kp = ks + hoff;
            const float* vp = vs + hoff;
            const float* wa = wf + (0 * 9 + t) * 64 + sb;
            const float* wb = wf + (1 * 9 + t) * 64 + sb;
            const float* wc = wf + (2 * 9 + t) * 64 + sb;
#pragma unroll
            for (int i = 0; i < 2; ++i) {
                float4 qv = *(const float4*)(qp + i * 32);
                float4 kv = *(const float4*)(kp + i * 32);
                float4 vv = *(const float4*)(vp + i * 32);
                float4 av = *(const float4*)(wa + i * 32);
                float4 bv = *(const float4*)(wb + i * 32);
                float4 cv = *(const float4*)(wc + i * 32);
                ocv[i * 4 + 0] += av.x * qv.x + bv.x * kv.x + cv.x * vv.x;
                ocv[i * 4 + 1] += av.y * qv.y + bv.y * kv.y + cv.y * vv.y;
                ocv[i * 4 + 2] += av.z * qv.z + bv.z * kv.z + cv.z * vv.z;
                ocv[i * 4 + 3] += av.w * qv.w + bv.w * kv.w + cv.w * vv.w;
            }
        }
    }

    const float r1 = rate1[0];
    const float r2 = rate2[0];
#pragma unroll
    for (int i = 0; i < 2; ++i)
#pragma unroll
        for (int j = 0; j < 4; ++j) {
            int ch = i * 32 + s * 4 + j;
            float res = r1 * (oa[i * 4 + j] * inv) +
                        r2 * (ocv[i * 4 + j] + __ldg(b_dep + ch));
            out[((size_t)(b * 64 + ch) * 56 + gy) * 56 + gx] = res;
        }
}

// ---------------- launch ----------------
extern "C" void kernel_launch(void* const* d_in, const int* in_sizes, int n_in,
                              void* d_out, int out_size) {
    const float* x    = (const float*)d_in[0];
    const float* w1   = (const float*)d_in[1];
    const float* b1   = (const float*)d_in[2];
    const float* w2   = (const float*)d_in[3];
    const float* b2   = (const float*)d_in[4];
    const float* w3   = (const float*)d_in[5];
    const float* b3   = (const float*)d_in[6];
    const float* wp   = (const float*)d_in[7];
    // d_in[8] = bp (cancels analytically)
    const float* w_fc = (const float*)d_in[9];
    const float* w_dep = (const float*)d_in[10];
    const float* b_dep = (const float*)d_in[11];
    const float* rate1 = (const float*)d_in[12];
    const float* rate2 = (const float*)d_in[13];
    float* out = (float*)d_out;

    const int qkv_smem = (4096 + 64 * WS_STRIDE + 192) * 4;
    const int att_smem = (3 * 144 * PSTR + 1728) * 4;
    cudaFuncSetAttribute(qkv_kernel, cudaFuncAttributeMaxDynamicSharedMemorySize, qkv_smem);
    cudaFuncSetAttribute(attn_kernel, cudaFuncAttributeMaxDynamicSharedMemorySize, att_smem);

    qkv_kernel<<<dim3(49, 8), 256, qkv_smem>>>(x, w1, b1, w2, b2, w3, b3);
    attn_kernel<<<dim3(7, 7, 8), 512, att_smem>>>(wp, w_fc, w_dep, b_dep, rate1, rate2, out);
}